// round 3
// baseline (speedup 1.0000x reference)
#include <cuda_runtime.h>
#include <math.h>

#define B_ 128
#define T_ 256
#define D_ 256
#define U_ 1024
#define J_ 2048  /* 2U */

__device__ float g_tau[U_];   // softplus(w_tau), 4KB

// ---------- packed f32x2 helpers (PTX-only path, doubles fp32 FMA rate) ----------
__device__ __forceinline__ void fma2(unsigned long long &acc,
                                     unsigned long long a,
                                     unsigned long long b) {
    asm("fma.rn.f32x2 %0, %1, %2, %0;" : "+l"(acc) : "l"(a), "l"(b));
}
__device__ __forceinline__ unsigned long long pack2(float lo, float hi) {
    unsigned long long r;
    asm("mov.b64 %0, {%1, %2};" : "=l"(r) : "f"(lo), "f"(hi));
    return r;
}
__device__ __forceinline__ void unpack2(unsigned long long v, float &lo, float &hi) {
    asm("mov.b64 {%0, %1}, %2;" : "=f"(lo), "=f"(hi) : "l"(v));
}

// ---------------- tau = softplus(w_tau), once ----------------
__global__ void tau_kernel(const float* __restrict__ w_tau) {
    int u = threadIdx.x;
    float w = w_tau[u];
    g_tau[u] = (w > 20.f) ? w : log1pf(expf(w));
}

// ---------------- one recurrent step (fused x-part) ----------------
// pre[b][c] = sum_k h[b][k]*Wh[k][col(c)] + sum_k x_t[b][k]*Wx[k][col(c)] + bias
// c in [0,64): c<32 -> f-col u0+c, c>=32 -> a-col U+u0+c-32.
// Tile: 32 batches x 64 pre-cols, 256 threads, per-thread 2 rows x 2 packed pairs.
__global__ void __launch_bounds__(256) step_kernel(
    const float* __restrict__ hprev, long hstride,
    const float* __restrict__ Wh,
    const float* __restrict__ Wx,
    const float* __restrict__ feats,
    const float* __restrict__ bias,
    const float* __restrict__ tsteps,
    float* __restrict__ out, int t)
{
    __shared__ unsigned long long sm_u64[4096];  // 32KB raw
    unsigned long long (*As2)[64] = (unsigned long long (*)[64])sm_u64;  // [32][64] {v,v}, 16KB
    float (*Ws)[64] = (float (*)[64])((char*)sm_u64 + 16384);            // [64][64], 16KB

    const int tid = threadIdx.x;
    const int cx  = tid & 15;     // pre-col group: local cols pc..pc+3
    const int ry  = tid >> 4;     // row pair: rows ry*2, ry*2+1
    const int u0  = blockIdx.x * 32;
    const int b0  = blockIdx.y * 32;
    const int pc  = cx * 4;

    unsigned long long acc00 = 0ull, acc01 = 0ull, acc10 = 0ull, acc11 = 0ull;

    // ----- phase 0: h @ Wh (K = 1024) ; phase 1: x_t @ Wx (K = 256) -----
#pragma unroll 1
    for (int phase = 0; phase < 2; phase++) {
        const int Ktot = (phase == 0) ? U_ : D_;
        const float* __restrict__ W = (phase == 0) ? Wh : Wx;
#pragma unroll 1
        for (int k0 = 0; k0 < Ktot; k0 += 64) {
#pragma unroll
            for (int i = 0; i < 8; i++) {            // A tile: 32 r x 64 kc
                int p = tid + i * 256;
                int r = p >> 6, kc = p & 63;
                float v;
                if (phase == 0)
                    v = hprev[(size_t)(b0 + r) * hstride + k0 + kc];
                else
                    v = feats[((size_t)(b0 + r) * T_ + t) * D_ + k0 + kc];
                As2[r][kc] = pack2(v, v);
            }
#pragma unroll
            for (int i = 0; i < 16; i++) {           // W tile: 64 kc x 64 c
                int p = tid + i * 256;
                int kc = p >> 6, c = p & 63;
                int col = (c < 32) ? (u0 + c) : (U_ + u0 + c - 32);
                Ws[kc][c] = W[(size_t)(k0 + kc) * J_ + col];
            }
            __syncthreads();
#pragma unroll 16
            for (int kc = 0; kc < 64; kc++) {
                unsigned long long w01 = *(const unsigned long long*)&Ws[kc][pc];
                unsigned long long w23 = *(const unsigned long long*)&Ws[kc][pc + 2];
                unsigned long long a0p = As2[ry * 2][kc];
                unsigned long long a1p = As2[ry * 2 + 1][kc];
                fma2(acc00, a0p, w01);
                fma2(acc01, a0p, w23);
                fma2(acc10, a1p, w01);
                fma2(acc11, a1p, w23);
            }
            __syncthreads();
        }
    }

    // dump pre tile to smem (reuse As2 region), then epilogue
    float* preS = (float*)sm_u64;  // [32][64]
    {
        float x0, x1, x2, x3;
        unpack2(acc00, x0, x1); unpack2(acc01, x2, x3);
        float* row0 = preS + (ry * 2) * 64 + pc;
        row0[0] = x0; row0[1] = x1; row0[2] = x2; row0[3] = x3;
        unpack2(acc10, x0, x1); unpack2(acc11, x2, x3);
        float* row1 = preS + (ry * 2 + 1) * 64 + pc;
        row1[0] = x0; row1[1] = x1; row1[2] = x2; row1[3] = x3;
    }
    __syncthreads();

#pragma unroll
    for (int i = 0; i < 4; i++) {
        int q = tid + i * 256;
        int r = q >> 5, ul = q & 31;
        int b = b0 + r;
        int u = u0 + ul;
        float pre_f = preS[r * 64 + ul]      + bias[u];
        float pre_a = preS[r * 64 + 32 + ul] + bias[U_ + u];
        float f = 1.f / (1.f + expf(-pre_f));
        float a = tanhf(pre_a);
        float dt = tsteps[(size_t)b * T_ + t];
        float hp = hprev[(size_t)b * hstride + u];
        float decay = expf(-dt * (g_tau[u] + f));
        out[((size_t)b * T_ + t) * (size_t)U_ + u] = (hp - a) * decay + a;
    }
}

extern "C" void kernel_launch(void* const* d_in, const int* in_sizes, int n_in,
                              void* d_out, int out_size) {
    (void)in_sizes; (void)n_in; (void)out_size;
    const float* feats  = (const float*)d_in[0];
    const float* tsteps = (const float*)d_in[1];
    const float* Wx     = (const float*)d_in[2];
    const float* Wh     = (const float*)d_in[3];
    const float* bias   = (const float*)d_in[4];
    const float* w_tau  = (const float*)d_in[5];
    const float* h0     = (const float*)d_in[6];
    float* out = (float*)d_out;

    tau_kernel<<<1, U_>>>(w_tau);

    for (int t = 0; t < T_; t++) {
        const float* hp = (t == 0) ? h0 : (out + (size_t)(t - 1) * U_);
        long hstride    = (t == 0) ? (long)U_ : (long)T_ * U_;
        step_kernel<<<dim3(U_ / 32, B_ / 32), 256>>>(hp, hstride, Wh, Wx, feats,
                                                     bias, tsteps, out, t);
    }
}

// round 7
// speedup vs baseline: 2.0358x; 2.0358x over previous
#include <cuda_runtime.h>
#include <cuda_bf16.h>
#include <math.h>
#include <stdint.h>

#define B_ 128
#define T_ 256
#define D_ 256
#define U_ 1024
#define J_ 2048

#define NT_ 64            /* N tiles of 32 cols (= 16 u each) */
#define NCH_ 20           /* K chunks of 64 (16 h + 4 x) */
#define AT_ELEMS 8192     /* A tile 128x64 bf16 */
#define WT_ELEMS 2048     /* W tile 32x64 bf16 */

// ---------------- static device buffers (pre-swizzled bf16 hi/lo tiles) ----------------
__device__ float g_tau[U_];
__device__ __align__(128) __nv_bfloat16 g_Wc_hi[NT_ * NCH_ * WT_ELEMS];  // 5.2MB
__device__ __align__(128) __nv_bfloat16 g_Wc_lo[NT_ * NCH_ * WT_ELEMS];
__device__ __align__(128) __nv_bfloat16 g_X_hi[T_ * 4 * AT_ELEMS];       // 16.8MB
__device__ __align__(128) __nv_bfloat16 g_X_lo[T_ * 4 * AT_ELEMS];
__device__ __align__(128) __nv_bfloat16 g_Ah_hi[2 * 16 * AT_ELEMS];      // 512KB
__device__ __align__(128) __nv_bfloat16 g_Ah_lo[2 * 16 * AT_ELEMS];

__device__ __forceinline__ uint32_t swz(uint32_t o) { return o ^ ((o >> 3) & 0x70); }

__device__ __forceinline__ uint32_t smem_u32(const void* p) {
    uint32_t a;
    asm("{ .reg .u64 t; cvta.to.shared.u64 t, %1; cvt.u32.u64 %0, t; }" : "=r"(a) : "l"(p));
    return a;
}

#define CP16(dst, src) \
    asm volatile("cp.async.cg.shared.global [%0], [%1], 16;" :: "r"(dst), "l"(src) : "memory")
#define CP_COMMIT() asm volatile("cp.async.commit_group;" ::: "memory")

#define LDSM4(r0, r1, r2, r3, addr) \
    asm volatile("ldmatrix.sync.aligned.m8n8.x4.shared.b16 {%0,%1,%2,%3}, [%4];" \
        : "=r"(r0), "=r"(r1), "=r"(r2), "=r"(r3) : "r"(addr))

#define MMA(C, a0, a1, a2, a3, b0, b1) \
    asm volatile("mma.sync.aligned.m16n8k16.row.col.f32.bf16.bf16.f32 " \
        "{%0,%1,%2,%3},{%4,%5,%6,%7},{%8,%9},{%0,%1,%2,%3};" \
        : "+f"((C)[0]), "+f"((C)[1]), "+f"((C)[2]), "+f"((C)[3]) \
        : "r"(a0), "r"(a1), "r"(a2), "r"(a3), "r"(b0), "r"(b1))

// ---------------- one-off prep kernels ----------------
__global__ void tau_kernel(const float* __restrict__ w_tau) {
    int u = threadIdx.x;
    float w = w_tau[u];
    g_tau[u] = (w > 20.f) ? w : log1pf(expf(w));
}

// Wc[nTile][chunk][r(32)][kc(64)] : n = nTile*32+r ; u = n>>1 ; col = (n&1)?1024+u:u
// k = chunk*64+kc ; src = k<1024 ? Wh[k][col] : Wx[k-1024][col]
__global__ void __launch_bounds__(256) prep_w(const float* __restrict__ Wh,
                                              const float* __restrict__ Wx) {
    int nTile = blockIdx.x, ch = blockIdx.y;
    char* dh = (char*)(g_Wc_hi + (nTile * NCH_ + ch) * WT_ELEMS);
    char* dl = (char*)(g_Wc_lo + (nTile * NCH_ + ch) * WT_ELEMS);
    for (int i = threadIdx.x; i < WT_ELEMS; i += 256) {
        int r = i >> 6, kc = i & 63;
        int n = nTile * 32 + r;
        int u = n >> 1;
        int col = (n & 1) ? (U_ + u) : u;
        int k = ch * 64 + kc;
        float v = (k < U_) ? Wh[(size_t)k * J_ + col] : Wx[(size_t)(k - U_) * J_ + col];
        __nv_bfloat16 hi = __float2bfloat16(v);
        __nv_bfloat16 lo = __float2bfloat16(v - __bfloat162float(hi));
        uint32_t off = swz((uint32_t)(r * 128 + kc * 2));
        *(__nv_bfloat16*)(dh + off) = hi;
        *(__nv_bfloat16*)(dl + off) = lo;
    }
}

// X[t][cx][m(128)][kc(64)] = feats[m][t][cx*64+kc]
__global__ void __launch_bounds__(256) prep_x(const float* __restrict__ feats) {
    int t = blockIdx.x, cx = blockIdx.y;
    char* dh = (char*)(g_X_hi + (t * 4 + cx) * AT_ELEMS);
    char* dl = (char*)(g_X_lo + (t * 4 + cx) * AT_ELEMS);
    for (int i = threadIdx.x; i < AT_ELEMS; i += 256) {
        int m = i >> 6, kc = i & 63;
        float v = feats[((size_t)m * T_ + t) * D_ + cx * 64 + kc];
        __nv_bfloat16 hi = __float2bfloat16(v);
        __nv_bfloat16 lo = __float2bfloat16(v - __bfloat162float(hi));
        uint32_t off = swz((uint32_t)(m * 128 + kc * 2));
        *(__nv_bfloat16*)(dh + off) = hi;
        *(__nv_bfloat16*)(dl + off) = lo;
    }
}

__global__ void __launch_bounds__(256) prep_h0(const float* __restrict__ h0) {
    int ch = blockIdx.x;  // 0..15, parity 0
    char* dh = (char*)(g_Ah_hi + ch * AT_ELEMS);
    char* dl = (char*)(g_Ah_lo + ch * AT_ELEMS);
    for (int i = threadIdx.x; i < AT_ELEMS; i += 256) {
        int m = i >> 6, kc = i & 63;
        float v = h0[(size_t)m * U_ + ch * 64 + kc];
        __nv_bfloat16 hi = __float2bfloat16(v);
        __nv_bfloat16 lo = __float2bfloat16(v - __bfloat162float(hi));
        uint32_t off = swz((uint32_t)(m * 128 + kc * 2));
        *(__nv_bfloat16*)(dh + off) = hi;
        *(__nv_bfloat16*)(dl + off) = lo;
    }
}

// ---------------- per-step HMMA GEMM + in-register LTC epilogue ----------------
// stage layout (40960 B): Ah @0 (16K), Al @16384, Wh @32768 (4K), Wl @36864 (4K)
#define STAGE_B 40960
#define NSTAGE 3
#define SMEM_TOTAL (NSTAGE * STAGE_B + 1024)

__global__ void __launch_bounds__(256) step_kernel(
    const float* __restrict__ hprev, long hstride,
    const float* __restrict__ bias,
    const float* __restrict__ tsteps,
    float* __restrict__ out, int t)
{
    extern __shared__ char smem[];
    uint32_t sb0 = (smem_u32(smem) + 1023u) & ~1023u;

    const int tid = threadIdx.x;
    const int wid = tid >> 5, lid = tid & 31;
    const int wm = wid & 3, wn = wid >> 2;
    const int nTile = blockIdx.x;
    const int par = t & 1;

    // per-lane ldmatrix address components
    const int rowA = wm * 32 + (lid & 15);
    const uint32_t rowAoff = (uint32_t)rowA * 128u;
    const uint32_t xrA = (uint32_t)(rowA & 7) << 4;
    const int rowW = wn * 16 + (lid & 15);
    const uint32_t rowWoff = (uint32_t)rowW * 128u;
    const uint32_t xrW = (uint32_t)(rowW & 7) << 4;
    const uint32_t kbsel = (uint32_t)(lid >> 4) << 4;

    float C00[4] = {0, 0, 0, 0}, C01[4] = {0, 0, 0, 0};
    float C10[4] = {0, 0, 0, 0}, C11[4] = {0, 0, 0, 0};

    // -------- cp.async chunk issue --------
    auto issue = [&](int c) {
        const uint32_t stg = sb0 + (uint32_t)(c % NSTAGE) * STAGE_B;
        const char *sAh, *sAl;
        if (c < 16) {
            sAh = (const char*)(g_Ah_hi + (par * 16 + c) * AT_ELEMS);
            sAl = (const char*)(g_Ah_lo + (par * 16 + c) * AT_ELEMS);
        } else {
            sAh = (const char*)(g_X_hi + (t * 4 + (c - 16)) * AT_ELEMS);
            sAl = (const char*)(g_X_lo + (t * 4 + (c - 16)) * AT_ELEMS);
        }
        const char* sWh = (const char*)(g_Wc_hi + (nTile * NCH_ + c) * WT_ELEMS);
        const char* sWl = (const char*)(g_Wc_lo + (nTile * NCH_ + c) * WT_ELEMS);
        const uint32_t o = (uint32_t)tid * 16u;
#pragma unroll
        for (int j = 0; j < 4; j++) CP16(stg + o + j * 4096, sAh + o + j * 4096);
#pragma unroll
        for (int j = 0; j < 4; j++) CP16(stg + 16384 + o + j * 4096, sAl + o + j * 4096);
        CP16(stg + 32768 + o, sWh + o);
        CP16(stg + 36864 + o, sWl + o);
        CP_COMMIT();
    };

    issue(0);
    issue(1);

#pragma unroll 1
    for (int c = 0; c < NCH_; c++) {
        if (c + 2 < NCH_) {
            issue(c + 2);
            asm volatile("cp.async.wait_group 2;" ::: "memory");
        } else if (c + 1 < NCH_) {
            asm volatile("cp.async.wait_group 1;" ::: "memory");
        } else {
            asm volatile("cp.async.wait_group 0;" ::: "memory");
        }
        __syncthreads();

        const uint32_t stg = sb0 + (uint32_t)(c % NSTAGE) * STAGE_B;
#pragma unroll
        for (int k16 = 0; k16 < 4; k16++) {
            const uint32_t kb = (uint32_t)k16 * 32u + kbsel;
            const uint32_t aA = stg + rowAoff + (kb ^ xrA);
            const uint32_t aW = stg + 32768 + rowWoff + (kb ^ xrW);
            uint32_t h0r, h1r, h2r, h3r, h4, h5, h6, h7;       // Ah mi0, mi1
            uint32_t l0, l1, l2, l3, l4, l5, l6, l7;           // Al mi0, mi1
            uint32_t w0, w1, w2, w3, x0, x1, x2, x3;           // Wh, Wl
            LDSM4(h0r, h1r, h2r, h3r, aA);
            LDSM4(h4, h5, h6, h7, aA + 2048);
            LDSM4(l0, l1, l2, l3, aA + 16384);
            LDSM4(l4, l5, l6, l7, aA + 16384 + 2048);
            LDSM4(w0, w1, w2, w3, aW);
            LDSM4(x0, x1, x2, x3, aW + 4096);
            // term 1: Ah * Wh
            MMA(C00, h0r, h1r, h2r, h3r, w0, w2);
            MMA(C01, h0r, h1r, h2r, h3r, w1, w3);
            MMA(C10, h4, h5, h6, h7, w0, w2);
            MMA(C11, h4, h5, h6, h7, w1, w3);
            // term 2: Ah * Wl
            MMA(C00, h0r, h1r, h2r, h3r, x0, x2);
            MMA(C01, h0r, h1r, h2r, h3r, x1, x3);
            MMA(C10, h4, h5, h6, h7, x0, x2);
            MMA(C11, h4, h5, h6, h7, x1, x3);
            // term 3: Al * Wh
            MMA(C00, l0, l1, l2, l3, w0, w2);
            MMA(C01, l0, l1, l2, l3, w1, w3);
            MMA(C10, l4, l5, l6, l7, w0, w2);
            MMA(C11, l4, l5, l6, l7, w1, w3);
        }
        __syncthreads();
    }

    // -------- epilogue: all in registers --------
    const int g = lid >> 2, tig = lid & 3;
    const int p1 = par ^ 1;
    float* Cm[2][2] = {{C00, C01}, {C10, C11}};

#pragma unroll
    for (int ni = 0; ni < 2; ni++) {
        const int u = nTile * 16 + wn * 8 + ni * 4 + tig;
        const float bf = bias[u];
        const float ba = bias[U_ + u];
        const float tau = g_tau[u];
        const int chs = u >> 6, kc = u & 63;
        char* th = (char*)(g_Ah_hi + (p1 * 16 + chs) * AT_ELEMS);
        char* tl = (char*)(g_Ah_lo + (p1 * 16 + chs) * AT_ELEMS);
#pragma unroll
        for (int mi = 0; mi < 2; mi++) {
#pragma unroll
            for (int half = 0; half < 2; half++) {
                const int m = wm * 32 + mi * 16 + half * 8 + g;
                float pre_f = Cm[mi][ni][half * 2 + 0] + bf;
                float pre_a = Cm[mi][ni][half * 2 + 1] + ba;
                float f = 1.f / (1.f + expf(-pre_f));
                float a = tanhf(pre_a);
                float dtv = tsteps[(size_t)m * T_ + t];
                float hp = hprev[(size_t)m * hstride + u];
                float hn = (hp - a) * expf(-dtv * (tau + f)) + a;
                out[((size_t)m * T_ + t) * U_ + u] = hn;
                __nv_bfloat16 hi = __float2bfloat16(hn);
                __nv_bfloat16 lo = __float2bfloat16(hn - __bfloat162float(hi));
                uint32_t off = (uint32_t)(m * 128 + kc * 2);
                off ^= (off >> 3) & 0x70;
                *(__nv_bfloat16*)(th + off) = hi;
                *(__nv_bfloat16*)(tl + off) = lo;
            }
        }
    }
}

// ---------------- launch ----------------
extern "C" void kernel_launch(void* const* d_in, const int* in_sizes, int n_in,
                              void* d_out, int out_size) {
    (void)in_sizes; (void)n_in; (void)out_size;
    const float* feats  = (const float*)d_in[0];
    const float* tsteps = (const float*)d_in[1];
    const float* Wx     = (const float*)d_in[2];
    const float* Wh     = (const float*)d_in[3];
    const float* bias   = (const float*)d_in[4];
    const float* w_tau  = (const float*)d_in[5];
    const float* h0     = (const float*)d_in[6];
    float* out = (float*)d_out;

    static int smem_set = 0;
    if (!smem_set) {
        cudaFuncSetAttribute(step_kernel, cudaFuncAttributeMaxDynamicSharedMemorySize, SMEM_TOTAL);
        smem_set = 1;
    }

    tau_kernel<<<1, U_>>>(w_tau);
    prep_w<<<dim3(NT_, NCH_), 256>>>(Wh, Wx);
    prep_x<<<dim3(T_, 4), 256>>>(feats);
    prep_h0<<<16, 256>>>(h0);

    for (int t = 0; t < T_; t++) {
        const float* hp = (t == 0) ? h0 : (out + (size_t)(t - 1) * U_);
        long hstride    = (t == 0) ? (long)U_ : (long)T_ * U_;
        step_kernel<<<NT_, 256, SMEM_TOTAL>>>(hp, hstride, bias, tsteps, out, t);
    }
}

// round 8
// speedup vs baseline: 6.1211x; 3.0067x over previous
#include <cuda_runtime.h>
#include <cuda_bf16.h>
#include <math.h>
#include <stdint.h>

#define B_ 128
#define T_ 256
#define D_ 256
#define U_ 1024
#define J_ 2048

#define NT_ 64            /* N tiles of 32 pre-cols (= 16 u each) */
#define NCH_ 20           /* K chunks of 64 (16 h + 4 x) */
#define AT_ELEMS 8192     /* A tile 128x64 bf16 */
#define WT_ELEMS 2048     /* W tile 32x64 bf16 */

// ---------------- static device buffers (pre-swizzled bf16 hi/lo tiles) ----------------
__device__ float g_tau[U_];
__device__ __align__(128) __nv_bfloat16 g_Wc_hi[NT_ * NCH_ * WT_ELEMS];  // 5.2MB
__device__ __align__(128) __nv_bfloat16 g_Wc_lo[NT_ * NCH_ * WT_ELEMS];
__device__ __align__(128) __nv_bfloat16 g_X_hi[T_ * 4 * AT_ELEMS];       // 16.8MB
__device__ __align__(128) __nv_bfloat16 g_X_lo[T_ * 4 * AT_ELEMS];
__device__ __align__(128) __nv_bfloat16 g_Ah_hi[2 * 16 * AT_ELEMS];      // 512KB
__device__ __align__(128) __nv_bfloat16 g_Ah_lo[2 * 16 * AT_ELEMS];
__device__ unsigned g_cnt[2 * T_];   // per-step half-grid barrier counters

__device__ __forceinline__ uint32_t swz(uint32_t o) { return o ^ ((o >> 3) & 0x70); }

__device__ __forceinline__ uint32_t smem_u32(const void* p) {
    uint32_t a;
    asm("{ .reg .u64 t; cvta.to.shared.u64 t, %1; cvt.u32.u64 %0, t; }" : "=r"(a) : "l"(p));
    return a;
}

#define CP16(dst, src) \
    asm volatile("cp.async.cg.shared.global [%0], [%1], 16;" :: "r"(dst), "l"(src) : "memory")
#define CP_COMMIT() asm volatile("cp.async.commit_group;" ::: "memory")

#define LDSM4(r0, r1, r2, r3, addr) \
    asm volatile("ldmatrix.sync.aligned.m8n8.x4.shared.b16 {%0,%1,%2,%3}, [%4];" \
        : "=r"(r0), "=r"(r1), "=r"(r2), "=r"(r3) : "r"(addr))

#define MMA(C, a0, a1, a2, a3, b0, b1) \
    asm volatile("mma.sync.aligned.m16n8k16.row.col.f32.bf16.bf16.f32 " \
        "{%0,%1,%2,%3},{%4,%5,%6,%7},{%8,%9},{%0,%1,%2,%3};" \
        : "+f"((C)[0]), "+f"((C)[1]), "+f"((C)[2]), "+f"((C)[3]) \
        : "r"(a0), "r"(a1), "r"(a2), "r"(a3), "r"(b0), "r"(b1))

// ---------------- one-off prep kernels ----------------
__global__ void reset_kernel() {
    if (threadIdx.x < 2 * T_) g_cnt[threadIdx.x] = 0;
}

__global__ void tau_kernel(const float* __restrict__ w_tau) {
    int u = threadIdx.x;
    float w = w_tau[u];
    g_tau[u] = (w > 20.f) ? w : log1pf(expf(w));
}

__global__ void __launch_bounds__(256) prep_w(const float* __restrict__ Wh,
                                              const float* __restrict__ Wx) {
    int nTile = blockIdx.x, ch = blockIdx.y;
    char* dh = (char*)(g_Wc_hi + (nTile * NCH_ + ch) * WT_ELEMS);
    char* dl = (char*)(g_Wc_lo + (nTile * NCH_ + ch) * WT_ELEMS);
    for (int i = threadIdx.x; i < WT_ELEMS; i += 256) {
        int r = i >> 6, kc = i & 63;
        int n = nTile * 32 + r;
        int u = n >> 1;
        int col = (n & 1) ? (U_ + u) : u;
        int k = ch * 64 + kc;
        float v = (k < U_) ? Wh[(size_t)k * J_ + col] : Wx[(size_t)(k - U_) * J_ + col];
        __nv_bfloat16 hi = __float2bfloat16(v);
        __nv_bfloat16 lo = __float2bfloat16(v - __bfloat162float(hi));
        uint32_t off = swz((uint32_t)(r * 128 + kc * 2));
        *(__nv_bfloat16*)(dh + off) = hi;
        *(__nv_bfloat16*)(dl + off) = lo;
    }
}

__global__ void __launch_bounds__(256) prep_x(const float* __restrict__ feats) {
    int t = blockIdx.x, cx = blockIdx.y;
    char* dh = (char*)(g_X_hi + (t * 4 + cx) * AT_ELEMS);
    char* dl = (char*)(g_X_lo + (t * 4 + cx) * AT_ELEMS);
    for (int i = threadIdx.x; i < AT_ELEMS; i += 256) {
        int m = i >> 6, kc = i & 63;
        float v = feats[((size_t)m * T_ + t) * D_ + cx * 64 + kc];
        __nv_bfloat16 hi = __float2bfloat16(v);
        __nv_bfloat16 lo = __float2bfloat16(v - __bfloat162float(hi));
        uint32_t off = swz((uint32_t)(m * 128 + kc * 2));
        *(__nv_bfloat16*)(dh + off) = hi;
        *(__nv_bfloat16*)(dl + off) = lo;
    }
}

__global__ void __launch_bounds__(256) prep_h0(const float* __restrict__ h0) {
    int ch = blockIdx.x;  // 0..15, parity 0
    char* dh = (char*)(g_Ah_hi + ch * AT_ELEMS);
    char* dl = (char*)(g_Ah_lo + ch * AT_ELEMS);
    for (int i = threadIdx.x; i < AT_ELEMS; i += 256) {
        int m = i >> 6, kc = i & 63;
        float v = h0[(size_t)m * U_ + ch * 64 + kc];
        __nv_bfloat16 hi = __float2bfloat16(v);
        __nv_bfloat16 lo = __float2bfloat16(v - __bfloat162float(hi));
        uint32_t off = swz((uint32_t)(m * 128 + kc * 2));
        *(__nv_bfloat16*)(dh + off) = hi;
        *(__nv_bfloat16*)(dl + off) = lo;
    }
}

// ---------------- persistent kernel: all 256 steps ----------------
// smem: A stages 3 x 16KB (Ah 8K + Al 8K) @0 ; W resident 20 x 8KB (Wh 4K + Wl 4K) @49152
#define A_STAGE_B 16384
#define W_BASE    49152
#define SMEM_TOTAL (49152 + NCH_ * 8192 + 1024)

__global__ void __launch_bounds__(256, 1) rnn_kernel(
    const float* __restrict__ h0,
    const float* __restrict__ bias,
    const float* __restrict__ tsteps,
    float* __restrict__ out)
{
    extern __shared__ char smem[];
    const uint32_t sA = (smem_u32(smem) + 1023u) & ~1023u;
    const uint32_t sW = sA + W_BASE;

    const int tid = threadIdx.x;
    const int wid = tid >> 5, lid = tid & 31;
    const int wm = wid & 3, wn = wid >> 2;        // warp tile 16 rows x 16 cols
    const int bid = blockIdx.x;
    const int mh = bid >> 6;                      // M-half (independent halves)
    const int nt = bid & 63;                      // N tile (32 pre-cols = 16 u)

    // ---- load resident W tiles (one-time) ----
    {
        const uint32_t o = (uint32_t)tid * 16u;
#pragma unroll
        for (int c = 0; c < NCH_; c++) {
            const uint32_t wst = sW + (uint32_t)c * 8192u;
            CP16(wst + o, (const char*)(g_Wc_hi + (nt * NCH_ + c) * WT_ELEMS) + o);
            CP16(wst + 4096 + o, (const char*)(g_Wc_lo + (nt * NCH_ + c) * WT_ELEMS) + o);
        }
        CP_COMMIT();
        asm volatile("cp.async.wait_group 0;" ::: "memory");
        __syncthreads();
    }

    // ---- per-thread constants & persistent h state ----
    const int g = lid >> 2, q = lid & 3;
    const int mBase = mh * 64 + wm * 16 + g;      // rows mBase, mBase+8
    int ua[2]; float bf[2], ba[2], tauv[2];
#pragma unroll
    for (int blk = 0; blk < 2; blk++) {
        ua[blk]   = nt * 16 + wn * 8 + blk * 4 + q;
        bf[blk]   = bias[ua[blk]];
        ba[blk]   = bias[U_ + ua[blk]];
        tauv[blk] = g_tau[ua[blk]];
    }
    float hp[4];  // [blk*2 + rr]
#pragma unroll
    for (int blk = 0; blk < 2; blk++)
#pragma unroll
        for (int rr = 0; rr < 2; rr++)
            hp[blk * 2 + rr] = h0[(size_t)(mBase + rr * 8) * U_ + ua[blk]];

    // ldmatrix address components
    const int rowA = wm * 16 + (lid & 15);        // 0..63
    const uint32_t rowAoff = (uint32_t)rowA * 128u;
    const uint32_t xrA = (uint32_t)(rowA & 7) << 4;
    const int rowW = wn * 16 + (lid & 15);        // 0..31
    const uint32_t rowWoff = (uint32_t)rowW * 128u;
    const uint32_t xrW = (uint32_t)(rowW & 7) << 4;
    const uint32_t kbsel = (uint32_t)(lid >> 4) << 4;

    const uint32_t aOff = (uint32_t)tid * 16u;

    float C0[4] = {0, 0, 0, 0}, C1[4] = {0, 0, 0, 0};

#pragma unroll 1
    for (int t = 0; t < T_; t++) {
        const int par = t & 1;
        const int p1 = par ^ 1;

        // A-chunk issue (16KB: Ah 8K + Al 8K; rows mh*64..+64 are contiguous 8KB slices)
        auto issueA = [&](int c) {
            const uint32_t stg = sA + (uint32_t)(c % 3) * A_STAGE_B;
            const char *sh, *sl;
            if (c < 16) {
                sh = (const char*)(g_Ah_hi + (par * 16 + c) * AT_ELEMS) + mh * 8192;
                sl = (const char*)(g_Ah_lo + (par * 16 + c) * AT_ELEMS) + mh * 8192;
            } else {
                sh = (const char*)(g_X_hi + (t * 4 + (c - 16)) * AT_ELEMS) + mh * 8192;
                sl = (const char*)(g_X_lo + (t * 4 + (c - 16)) * AT_ELEMS) + mh * 8192;
            }
            CP16(stg + aOff, sh + aOff);
            CP16(stg + 4096 + aOff, sh + 4096 + aOff);
            CP16(stg + 8192 + aOff, sl + aOff);
            CP16(stg + 12288 + aOff, sl + 4096 + aOff);
            CP_COMMIT();
        };

        issueA(0);
        issueA(1);

#pragma unroll 1
        for (int c = 0; c < NCH_; c++) {
            if (c + 2 < NCH_) {
                issueA(c + 2);
                asm volatile("cp.async.wait_group 2;" ::: "memory");
            } else if (c + 1 < NCH_) {
                asm volatile("cp.async.wait_group 1;" ::: "memory");
            } else {
                asm volatile("cp.async.wait_group 0;" ::: "memory");
            }
            __syncthreads();

            const uint32_t stg = sA + (uint32_t)(c % 3) * A_STAGE_B;
            const uint32_t wst = sW + (uint32_t)c * 8192u;
#pragma unroll
            for (int k16 = 0; k16 < 4; k16++) {
                const uint32_t kb = (uint32_t)k16 * 32u + kbsel;
                const uint32_t aA = stg + rowAoff + (kb ^ xrA);
                const uint32_t aW = wst + rowWoff + (kb ^ xrW);
                uint32_t a0, a1, a2, a3, e0, e1, e2, e3;
                uint32_t w0, w1, w2, w3, x0, x1, x2, x3;
                LDSM4(a0, a1, a2, a3, aA);             // A hi
                LDSM4(e0, e1, e2, e3, aA + 8192);      // A lo
                LDSM4(w0, w1, w2, w3, aW);             // W hi
                LDSM4(x0, x1, x2, x3, aW + 4096);      // W lo
                MMA(C0, a0, a1, a2, a3, w0, w2);
                MMA(C1, a0, a1, a2, a3, w1, w3);
                MMA(C0, a0, a1, a2, a3, x0, x2);
                MMA(C1, a0, a1, a2, a3, x1, x3);
                MMA(C0, e0, e1, e2, e3, w0, w2);
                MMA(C1, e0, e1, e2, e3, w1, w3);
            }
            __syncthreads();
        }

        // ---- LTC epilogue (registers only) ----
        const float dt0 = __ldg(&tsteps[(size_t)mBase * T_ + t]);
        const float dt1 = __ldg(&tsteps[(size_t)(mBase + 8) * T_ + t]);
        float* Cb[2] = {C0, C1};
#pragma unroll
        for (int blk = 0; blk < 2; blk++) {
            const int u = ua[blk];
            char* th = (char*)(g_Ah_hi + (p1 * 16 + (u >> 6)) * AT_ELEMS);
            char* tl = (char*)(g_Ah_lo + (p1 * 16 + (u >> 6)) * AT_ELEMS);
#pragma unroll
            for (int rr = 0; rr < 2; rr++) {
                const int m = mBase + rr * 8;
                float pre_f = Cb[blk][rr * 2 + 0] + bf[blk];
                float pre_a = Cb[blk][rr * 2 + 1] + ba[blk];
                float f = 1.f / (1.f + expf(-pre_f));
                float a = tanhf(pre_a);
                float dtv = rr ? dt1 : dt0;
                float hn = (hp[blk * 2 + rr] - a) * expf(-dtv * (tauv[blk] + f)) + a;
                hp[blk * 2 + rr] = hn;
                out[((size_t)m * T_ + t) * U_ + u] = hn;
                __nv_bfloat16 hi = __float2bfloat16(hn);
                __nv_bfloat16 lo = __float2bfloat16(hn - __bfloat162float(hi));
                uint32_t off = swz((uint32_t)(m * 128 + (u & 63) * 2));
                *(__nv_bfloat16*)(th + off) = hi;
                *(__nv_bfloat16*)(tl + off) = lo;
                Cb[blk][rr * 2 + 0] = 0.f;
                Cb[blk][rr * 2 + 1] = 0.f;
            }
        }

        // ---- half-grid barrier (64 CTAs of this M-half) ----
        if (t + 1 < T_) {
            __syncthreads();
            if (tid == 0) {
                unsigned* cp = &g_cnt[(unsigned)t * 2u + (unsigned)mh];
                asm volatile("fence.acq_rel.gpu;" ::: "memory");
                asm volatile("red.release.gpu.global.add.u32 [%0], %1;" :: "l"(cp), "r"(1u) : "memory");
                unsigned v;
                do {
                    asm volatile("ld.acquire.gpu.global.u32 %0, [%1];" : "=r"(v) : "l"(cp) : "memory");
                } while (v < 64u);
            }
            __syncthreads();
        }
    }
}

// ---------------- launch ----------------
extern "C" void kernel_launch(void* const* d_in, const int* in_sizes, int n_in,
                              void* d_out, int out_size) {
    (void)in_sizes; (void)n_in; (void)out_size;
    const float* feats  = (const float*)d_in[0];
    const float* tsteps = (const float*)d_in[1];
    const float* Wx     = (const float*)d_in[2];
    const float* Wh     = (const float*)d_in[3];
    const float* bias   = (const float*)d_in[4];
    const float* w_tau  = (const float*)d_in[5];
    const float* h0     = (const float*)d_in[6];
    float* out = (float*)d_out;

    static int smem_set = 0;
    if (!smem_set) {
        cudaFuncSetAttribute(rnn_kernel, cudaFuncAttributeMaxDynamicSharedMemorySize, SMEM_TOTAL);
        smem_set = 1;
    }

    reset_kernel<<<1, 512>>>();
    tau_kernel<<<1, U_>>>(w_tau);
    prep_w<<<dim3(NT_, NCH_), 256>>>(Wh, Wx);
    prep_x<<<dim3(T_, 4), 256>>>(feats);
    prep_h0<<<16, 256>>>(h0);

    rnn_kernel<<<128, 256, SMEM_TOTAL>>>(h0, bias, tsteps, out);
}